// round 1
// baseline (speedup 1.0000x reference)
#include <cuda_runtime.h>
#include <cuda_bf16.h>
#include <cstdint>

// Problem constants
#define B_   2
#define S_   2048
#define HID_ 4096
#define NH_  32
#define NKV_ 8
#define HD_  128
#define NREP_ 4
#define SCALING_ 0.08838834764831843f   // 128^-0.5

// Scratch (static device allocations are allowed)
__device__ float g_q[(size_t)B_ * S_ * NH_  * HD_];   // 67 MB
__device__ float g_k[(size_t)B_ * S_ * NKV_ * HD_];   // 16.8 MB
__device__ float g_v[(size_t)B_ * S_ * NKV_ * HD_];   // 16.8 MB
__device__ float g_o[(size_t)B_ * S_ * NH_  * HD_];   // 67 MB

// ---------------------------------------------------------------------------
// NT GEMM: C[M,N] = A[M,K] * W[N,K]^T   (both row-major, K contiguous)
// 128x128 block, BK=16, 256 threads, 8x8 per-thread micro-tile.
// ---------------------------------------------------------------------------
#define GBM 128
#define GBN 128
#define GBK 16

__global__ __launch_bounds__(256, 2)
void gemm_nt(const float* __restrict__ A, const float* __restrict__ W,
             float* __restrict__ C, int M, int N, int K) {
    __shared__ float As[GBK][GBM + 4];
    __shared__ float Bs[GBK][GBN + 4];

    const int tid = threadIdx.x;
    const int bm = blockIdx.y * GBM;
    const int bn = blockIdx.x * GBN;
    const int ty = tid >> 4;          // 0..15
    const int tx = tid & 15;          // 0..15

    float acc[8][8];
#pragma unroll
    for (int i = 0; i < 8; i++)
#pragma unroll
        for (int j = 0; j < 8; j++) acc[i][j] = 0.f;

    for (int k0 = 0; k0 < K; k0 += GBK) {
        // Load A tile (128x16 = 512 float4, 2 per thread), transpose into As[k][m]
#pragma unroll
        for (int i = 0; i < 2; i++) {
            int idx = tid + i * 256;
            int m = idx >> 2, kq = idx & 3;
            float4 v = *(const float4*)(A + (size_t)(bm + m) * K + k0 + kq * 4);
            As[kq * 4 + 0][m] = v.x;
            As[kq * 4 + 1][m] = v.y;
            As[kq * 4 + 2][m] = v.z;
            As[kq * 4 + 3][m] = v.w;
        }
#pragma unroll
        for (int i = 0; i < 2; i++) {
            int idx = tid + i * 256;
            int n = idx >> 2, kq = idx & 3;
            float4 v = *(const float4*)(W + (size_t)(bn + n) * K + k0 + kq * 4);
            Bs[kq * 4 + 0][n] = v.x;
            Bs[kq * 4 + 1][n] = v.y;
            Bs[kq * 4 + 2][n] = v.z;
            Bs[kq * 4 + 3][n] = v.w;
        }
        __syncthreads();

#pragma unroll
        for (int k = 0; k < GBK; k++) {
            float a[8], b[8];
#pragma unroll
            for (int i = 0; i < 8; i++) a[i] = As[k][ty * 8 + i];
#pragma unroll
            for (int i = 0; i < 8; i++) b[i] = Bs[k][tx * 8 + i];
#pragma unroll
            for (int i = 0; i < 8; i++)
#pragma unroll
                for (int j = 0; j < 8; j++)
                    acc[i][j] += a[i] * b[j];
        }
        __syncthreads();
    }

#pragma unroll
    for (int i = 0; i < 8; i++) {
        float* dst = C + (size_t)(bm + ty * 8 + i) * N + bn + tx * 8;
        float4 v0 = make_float4(acc[i][0], acc[i][1], acc[i][2], acc[i][3]);
        float4 v1 = make_float4(acc[i][4], acc[i][5], acc[i][6], acc[i][7]);
        ((float4*)dst)[0] = v0;
        ((float4*)dst)[1] = v1;
    }
}

// ---------------------------------------------------------------------------
// RoPE in-place: x layout [B*S, nheads*HD]; cos/sin layout [B*S, HD]
// one thread per (bs, head, pair d<64)
// ---------------------------------------------------------------------------
__global__ void rope_kernel(float* __restrict__ x,
                            const float* __restrict__ cosp,
                            const float* __restrict__ sinp,
                            int nheads, int total) {
    int idx = blockIdx.x * blockDim.x + threadIdx.x;
    if (idx >= total) return;
    int d  = idx & 63;
    int h  = (idx >> 6) % nheads;
    int bs = idx / (64 * nheads);
    float* row = x + (size_t)bs * nheads * HD_ + (size_t)h * HD_;
    const float* c = cosp + (size_t)bs * HD_;
    const float* s = sinp + (size_t)bs * HD_;
    float x1 = row[d], x2 = row[d + 64];
    row[d]      = x1 * c[d]      - x2 * s[d];
    row[d + 64] = x2 * c[d + 64] + x1 * s[d + 64];
}

// ---------------------------------------------------------------------------
// Flash attention (causal, GQA), fp32, online softmax.
// Block: 128 threads = 4 warps. 64 query rows/block; 2 threads per row,
// each owning 64 of 128 head dims (combined via shfl_xor lane^1).
// Key/Value tiles of 32 rows staged in SMEM.
// Q/K/V/O layout: [B*S, nheads*HD] (row = b*S+s, col = h*HD+d).
// ---------------------------------------------------------------------------
#define FBM 64
#define FBN 32

__global__ __launch_bounds__(128, 2)
void flash_kernel(const float* __restrict__ Q, const float* __restrict__ K,
                  const float* __restrict__ V, float* __restrict__ O) {
    __shared__ float Ksh[FBN][HD_];
    __shared__ float Vsh[FBN][HD_];

    const int b = blockIdx.z, h = blockIdx.y;
    const int qs = blockIdx.x * FBM;
    const int hk = h / NREP_;
    const int tid = threadIdx.x;
    const int lane = tid & 31, warp = tid >> 5;
    const int row  = qs + warp * 16 + (lane >> 1);
    const int half = lane & 1;

    // Load this thread's half of its Q row into registers, pre-scaled.
    const float* qptr = Q + (((size_t)(b * S_ + row)) * NH_ + h) * HD_ + half * 64;
    float4 qreg[16];
#pragma unroll
    for (int i = 0; i < 16; i++) {
        float4 v = ((const float4*)qptr)[i];
        v.x *= SCALING_; v.y *= SCALING_; v.z *= SCALING_; v.w *= SCALING_;
        qreg[i] = v;
    }

    float acc[64];
#pragma unroll
    for (int i = 0; i < 64; i++) acc[i] = 0.f;
    float m = -1e30f, l = 0.f;

    const int ntiles = (qs + FBM) / FBN;
    for (int j = 0; j < ntiles; j++) {
        const int ks = j * FBN;
        // Cooperative K/V tile load: 32 rows x 32 float4 each; 8 float4/thread.
        {
            int r  = tid >> 2;
            int cq = tid & 3;
            const float* kg = K + (((size_t)(b * S_ + ks + r)) * NKV_ + hk) * HD_;
            const float* vg = V + (((size_t)(b * S_ + ks + r)) * NKV_ + hk) * HD_;
#pragma unroll
            for (int i = 0; i < 8; i++) {
                int c4 = cq + i * 4;
                ((float4*)Ksh[r])[c4] = ((const float4*)kg)[c4];
                ((float4*)Vsh[r])[c4] = ((const float4*)vg)[c4];
            }
        }
        __syncthreads();

        // Scores for 32 keys (each thread does its 64-dim partial, pair-combined)
        float p[FBN];
        float mt = m;
#pragma unroll
        for (int c = 0; c < FBN; c++) {
            const float4* kr = (const float4*)(&Ksh[c][half * 64]);
            float s = 0.f;
#pragma unroll
            for (int i = 0; i < 16; i++) {
                float4 kv = kr[i];
                s += qreg[i].x * kv.x + qreg[i].y * kv.y
                   + qreg[i].z * kv.z + qreg[i].w * kv.w;
            }
            s += __shfl_xor_sync(0xffffffffu, s, 1);
            if (ks + c > row) s = -1e30f;
            p[c] = s;
            mt = fmaxf(mt, s);
        }

        const float scale = __expf(m - mt);
        m = mt;
        l *= scale;
#pragma unroll
        for (int i = 0; i < 64; i++) acc[i] *= scale;

#pragma unroll
        for (int c = 0; c < FBN; c++) {
            float pc = __expf(p[c] - mt);
            l += pc;
            const float4* vr = (const float4*)(&Vsh[c][half * 64]);
#pragma unroll
            for (int i = 0; i < 16; i++) {
                float4 vv = vr[i];
                acc[i * 4 + 0] += pc * vv.x;
                acc[i * 4 + 1] += pc * vv.y;
                acc[i * 4 + 2] += pc * vv.z;
                acc[i * 4 + 3] += pc * vv.w;
            }
        }
        __syncthreads();
    }

    const float inv = 1.f / l;
    float* optr = O + (((size_t)(b * S_ + row)) * NH_ + h) * HD_ + half * 64;
#pragma unroll
    for (int i = 0; i < 16; i++) {
        float4 o = make_float4(acc[i * 4 + 0] * inv, acc[i * 4 + 1] * inv,
                               acc[i * 4 + 2] * inv, acc[i * 4 + 3] * inv);
        ((float4*)optr)[i] = o;
    }
}

// ---------------------------------------------------------------------------
// Launch
// Inputs: 0=hidden_states, 1=cos, 2=sin, 3=attention_mask(unused, known causal),
//         4=Wq, 5=Wk, 6=Wv, 7=Wo. Output: fp32 [B,S,HID].
// ---------------------------------------------------------------------------
extern "C" void kernel_launch(void* const* d_in, const int* in_sizes, int n_in,
                              void* d_out, int out_size) {
    const float* hs   = (const float*)d_in[0];
    const float* cosp = (const float*)d_in[1];
    const float* sinp = (const float*)d_in[2];
    const float* Wq   = (const float*)d_in[4];
    const float* Wk   = (const float*)d_in[5];
    const float* Wv   = (const float*)d_in[6];
    const float* Wo   = (const float*)d_in[7];
    float* out = (float*)d_out;

    float *qbuf, *kbuf, *vbuf, *obuf;
    cudaGetSymbolAddress((void**)&qbuf, g_q);
    cudaGetSymbolAddress((void**)&kbuf, g_k);
    cudaGetSymbolAddress((void**)&vbuf, g_v);
    cudaGetSymbolAddress((void**)&obuf, g_o);

    const int M = B_ * S_;   // 4096

    // QKV projections
    gemm_nt<<<dim3((NH_ * HD_) / GBN, M / GBM), 256>>>(hs, Wq, qbuf, M, NH_ * HD_, HID_);
    gemm_nt<<<dim3((NKV_ * HD_) / GBN, M / GBM), 256>>>(hs, Wk, kbuf, M, NKV_ * HD_, HID_);
    gemm_nt<<<dim3((NKV_ * HD_) / GBN, M / GBM), 256>>>(hs, Wv, vbuf, M, NKV_ * HD_, HID_);

    // RoPE on Q and K
    {
        int totq = B_ * S_ * NH_ * 64;
        rope_kernel<<<(totq + 255) / 256, 256>>>(qbuf, cosp, sinp, NH_, totq);
        int totk = B_ * S_ * NKV_ * 64;
        rope_kernel<<<(totk + 255) / 256, 256>>>(kbuf, cosp, sinp, NKV_, totk);
    }

    // Causal GQA flash attention
    flash_kernel<<<dim3(S_ / FBM, NH_, B_), 128>>>(qbuf, kbuf, vbuf, obuf);

    // Output projection
    gemm_nt<<<dim3(HID_ / GBN, M / GBM), 256>>>(obuf, Wo, out, M, HID_, NH_ * HD_);
}

// round 2
// speedup vs baseline: 1.4469x; 1.4469x over previous
#include <cuda_runtime.h>
#include <cuda_bf16.h>
#include <cstdint>

// Problem constants
#define B_   2
#define S_   2048
#define HID_ 4096
#define NH_  32
#define NKV_ 8
#define HD_  128
#define NREP_ 4
#define SCALING_ 0.08838834764831843f   // 128^-0.5

// fp32 scratch
__device__ float g_q[(size_t)B_ * S_ * NH_  * HD_];
__device__ float g_k[(size_t)B_ * S_ * NKV_ * HD_];
__device__ float g_v[(size_t)B_ * S_ * NKV_ * HD_];
__device__ float g_o[(size_t)B_ * S_ * NH_  * HD_];

// bf16 split planes (hi / lo) for tensor-core GEMMs
#define HS_ELEMS  ((size_t)B_ * S_ * HID_)          // 16.78M
#define WQ_ELEMS  ((size_t)NH_ * HD_ * HID_)        // 16.78M
#define WK_ELEMS  ((size_t)NKV_ * HD_ * HID_)       // 4.19M
#define WO_ELEMS  ((size_t)HID_ * NH_ * HD_)        // 16.78M
__device__ __nv_bfloat16 g_hs_h[HS_ELEMS], g_hs_l[HS_ELEMS];
__device__ __nv_bfloat16 g_wq_h[WQ_ELEMS], g_wq_l[WQ_ELEMS];
__device__ __nv_bfloat16 g_wk_h[WK_ELEMS], g_wk_l[WK_ELEMS];
__device__ __nv_bfloat16 g_wv_h[WK_ELEMS], g_wv_l[WK_ELEMS];
__device__ __nv_bfloat16 g_wo_h[WO_ELEMS], g_wo_l[WO_ELEMS];
__device__ __nv_bfloat16 g_ob_h[HS_ELEMS], g_ob_l[HS_ELEMS];

// ---------------------------------------------------------------------------
// fp32 -> (bf16 hi, bf16 lo) split. lo = bf16(x - float(hi)).
// ---------------------------------------------------------------------------
__global__ void split_kernel(const float* __restrict__ x,
                             __nv_bfloat16* __restrict__ hi,
                             __nv_bfloat16* __restrict__ lo, size_t n) {
    size_t i = ((size_t)blockIdx.x * blockDim.x + threadIdx.x) * 4;
    if (i >= n) return;
    float4 v = *(const float4*)(x + i);
    float f[4] = {v.x, v.y, v.z, v.w};
#pragma unroll
    for (int j = 0; j < 4; j++) {
        __nv_bfloat16 h = __float2bfloat16(f[j]);
        hi[i + j] = h;
        lo[i + j] = __float2bfloat16(f[j] - __bfloat162float(h));
    }
}

// ---------------------------------------------------------------------------
// bf16 split-precision NT GEMM via mma.sync.m16n8k16 (fp32 accumulate)
// C[M,N] = A[M,K] * B[N,K]^T where A = Ah+Al, B = Bh+Bl
// 128x128 block, BK=32, 256 threads (8 warps as 2x4), warp tile 64x32.
// ---------------------------------------------------------------------------
#define BM 128
#define BN 128
#define BKb 32
#define PAD 40   // bf16 stride; (20*g + tg) mod 32 all-distinct -> conflict-free

__device__ __forceinline__ void mma16816(float c[4], uint32_t a0, uint32_t a1,
                                         uint32_t a2, uint32_t a3,
                                         uint32_t b0, uint32_t b1) {
    asm volatile(
        "mma.sync.aligned.m16n8k16.row.col.f32.bf16.bf16.f32 "
        "{%0,%1,%2,%3}, {%4,%5,%6,%7}, {%8,%9}, {%0,%1,%2,%3};\n"
        : "+f"(c[0]), "+f"(c[1]), "+f"(c[2]), "+f"(c[3])
        : "r"(a0), "r"(a1), "r"(a2), "r"(a3), "r"(b0), "r"(b1));
}

__global__ __launch_bounds__(256, 2)
void gemm_mma(const __nv_bfloat16* __restrict__ Ah, const __nv_bfloat16* __restrict__ Al,
              const __nv_bfloat16* __restrict__ Bh, const __nv_bfloat16* __restrict__ Bl,
              float* __restrict__ C, int M, int N, int K) {
    __shared__ __nv_bfloat16 As[2][BM][PAD];   // [plane][m][k]
    __shared__ __nv_bfloat16 Bs[2][BN][PAD];   // [plane][n][k]

    const int tid = threadIdx.x;
    const int warp = tid >> 5, lane = tid & 31;
    const int g = lane >> 2, tg = lane & 3;
    const int warpM = warp >> 2, warpN = warp & 3;    // 2 x 4 warp grid
    const int bm = blockIdx.y * BM, bn = blockIdx.x * BN;

    float c[4][4][4];
#pragma unroll
    for (int mi = 0; mi < 4; mi++)
#pragma unroll
        for (int ni = 0; ni < 4; ni++)
#pragma unroll
            for (int j = 0; j < 4; j++) c[mi][ni][j] = 0.f;

    for (int k0 = 0; k0 < K; k0 += BKb) {
        // Global -> SMEM: per plane 128 rows x 4 uint4; 2 per thread per plane.
#pragma unroll
        for (int i = 0; i < 2; i++) {
            int idx = tid + i * 256;          // 0..511
            int r = idx >> 2, c4 = idx & 3;
            size_t aoff = (size_t)(bm + r) * K + k0 + c4 * 8;
            size_t boff = (size_t)(bn + r) * K + k0 + c4 * 8;
            *(uint4*)(&As[0][r][c4 * 8]) = *(const uint4*)(Ah + aoff);
            *(uint4*)(&As[1][r][c4 * 8]) = *(const uint4*)(Al + aoff);
            *(uint4*)(&Bs[0][r][c4 * 8]) = *(const uint4*)(Bh + boff);
            *(uint4*)(&Bs[1][r][c4 * 8]) = *(const uint4*)(Bl + boff);
        }
        __syncthreads();

#pragma unroll
        for (int kk = 0; kk < 2; kk++) {
            const int kb = kk * 16;
            uint32_t aH[4][4], aL[4][4], bH[4][2], bL[4][2];
#pragma unroll
            for (int mi = 0; mi < 4; mi++) {
                int rb = warpM * 64 + mi * 16;
                const __nv_bfloat16* p0 = &As[0][rb + g][kb + 2 * tg];
                const __nv_bfloat16* p1 = &As[1][rb + g][kb + 2 * tg];
                aH[mi][0] = *(const uint32_t*)(p0);
                aH[mi][1] = *(const uint32_t*)(p0 + 8 * PAD);
                aH[mi][2] = *(const uint32_t*)(p0 + 8);
                aH[mi][3] = *(const uint32_t*)(p0 + 8 * PAD + 8);
                aL[mi][0] = *(const uint32_t*)(p1);
                aL[mi][1] = *(const uint32_t*)(p1 + 8 * PAD);
                aL[mi][2] = *(const uint32_t*)(p1 + 8);
                aL[mi][3] = *(const uint32_t*)(p1 + 8 * PAD + 8);
            }
#pragma unroll
            for (int ni = 0; ni < 4; ni++) {
                int nb = warpN * 32 + ni * 8;
                const __nv_bfloat16* p0 = &Bs[0][nb + g][kb + 2 * tg];
                const __nv_bfloat16* p1 = &Bs[1][nb + g][kb + 2 * tg];
                bH[ni][0] = *(const uint32_t*)(p0);
                bH[ni][1] = *(const uint32_t*)(p0 + 8);
                bL[ni][0] = *(const uint32_t*)(p1);
                bL[ni][1] = *(const uint32_t*)(p1 + 8);
            }
#pragma unroll
            for (int mi = 0; mi < 4; mi++)
#pragma unroll
                for (int ni = 0; ni < 4; ni++) {
                    mma16816(c[mi][ni], aH[mi][0], aH[mi][1], aH[mi][2], aH[mi][3],
                             bH[ni][0], bH[ni][1]);
                    mma16816(c[mi][ni], aH[mi][0], aH[mi][1], aH[mi][2], aH[mi][3],
                             bL[ni][0], bL[ni][1]);
                    mma16816(c[mi][ni], aL[mi][0], aL[mi][1], aL[mi][2], aL[mi][3],
                             bH[ni][0], bH[ni][1]);
                }
        }
        __syncthreads();
    }

    // Epilogue
#pragma unroll
    for (int mi = 0; mi < 4; mi++) {
        int r0 = bm + warpM * 64 + mi * 16 + g;
#pragma unroll
        for (int ni = 0; ni < 4; ni++) {
            int cc = bn + warpN * 32 + ni * 8 + 2 * tg;
            *(float2*)(C + (size_t)r0 * N + cc) = make_float2(c[mi][ni][0], c[mi][ni][1]);
            *(float2*)(C + (size_t)(r0 + 8) * N + cc) = make_float2(c[mi][ni][2], c[mi][ni][3]);
        }
    }
}

// ---------------------------------------------------------------------------
// RoPE in-place: x layout [B*S, nheads*HD]; cos/sin layout [B*S, HD]
// ---------------------------------------------------------------------------
__global__ void rope_kernel(float* __restrict__ x,
                            const float* __restrict__ cosp,
                            const float* __restrict__ sinp,
                            int nheads, int total) {
    int idx = blockIdx.x * blockDim.x + threadIdx.x;
    if (idx >= total) return;
    int d  = idx & 63;
    int h  = (idx >> 6) % nheads;
    int bs = idx / (64 * nheads);
    float* row = x + (size_t)bs * nheads * HD_ + (size_t)h * HD_;
    const float* c = cosp + (size_t)bs * HD_;
    const float* s = sinp + (size_t)bs * HD_;
    float x1 = row[d], x2 = row[d + 64];
    row[d]      = x1 * c[d]      - x2 * s[d];
    row[d + 64] = x2 * c[d + 64] + x1 * s[d + 64];
}

// ---------------------------------------------------------------------------
// Flash attention (causal, GQA), fp32, online softmax. (unchanged, correct)
// ---------------------------------------------------------------------------
#define FBM 64
#define FBN 32

__global__ __launch_bounds__(128, 2)
void flash_kernel(const float* __restrict__ Q, const float* __restrict__ K,
                  const float* __restrict__ V, float* __restrict__ O) {
    __shared__ float Ksh[FBN][HD_];
    __shared__ float Vsh[FBN][HD_];

    const int b = blockIdx.z, h = blockIdx.y;
    const int qs = blockIdx.x * FBM;
    const int hk = h / NREP_;
    const int tid = threadIdx.x;
    const int lane = tid & 31, warp = tid >> 5;
    const int row  = qs + warp * 16 + (lane >> 1);
    const int half = lane & 1;

    const float* qptr = Q + (((size_t)(b * S_ + row)) * NH_ + h) * HD_ + half * 64;
    float4 qreg[16];
#pragma unroll
    for (int i = 0; i < 16; i++) {
        float4 v = ((const float4*)qptr)[i];
        v.x *= SCALING_; v.y *= SCALING_; v.z *= SCALING_; v.w *= SCALING_;
        qreg[i] = v;
    }

    float acc[64];
#pragma unroll
    for (int i = 0; i < 64; i++) acc[i] = 0.f;
    float m = -1e30f, l = 0.f;

    const int ntiles = (qs + FBM) / FBN;
    for (int j = 0; j < ntiles; j++) {
        const int ks = j * FBN;
        {
            int r  = tid >> 2;
            int cq = tid & 3;
            const float* kg = K + (((size_t)(b * S_ + ks + r)) * NKV_ + hk) * HD_;
            const float* vg = V + (((size_t)(b * S_ + ks + r)) * NKV_ + hk) * HD_;
#pragma unroll
            for (int i = 0; i < 8; i++) {
                int c4 = cq + i * 4;
                ((float4*)Ksh[r])[c4] = ((const float4*)kg)[c4];
                ((float4*)Vsh[r])[c4] = ((const float4*)vg)[c4];
            }
        }
        __syncthreads();

        float p[FBN];
        float mt = m;
#pragma unroll
        for (int c = 0; c < FBN; c++) {
            const float4* kr = (const float4*)(&Ksh[c][half * 64]);
            float s = 0.f;
#pragma unroll
            for (int i = 0; i < 16; i++) {
                float4 kv = kr[i];
                s += qreg[i].x * kv.x + qreg[i].y * kv.y
                   + qreg[i].z * kv.z + qreg[i].w * kv.w;
            }
            s += __shfl_xor_sync(0xffffffffu, s, 1);
            if (ks + c > row) s = -1e30f;
            p[c] = s;
            mt = fmaxf(mt, s);
        }

        const float scale = __expf(m - mt);
        m = mt;
        l *= scale;
#pragma unroll
        for (int i = 0; i < 64; i++) acc[i] *= scale;

#pragma unroll
        for (int c = 0; c < FBN; c++) {
            float pc = __expf(p[c] - mt);
            l += pc;
            const float4* vr = (const float4*)(&Vsh[c][half * 64]);
#pragma unroll
            for (int i = 0; i < 16; i++) {
                float4 vv = vr[i];
                acc[i * 4 + 0] += pc * vv.x;
                acc[i * 4 + 1] += pc * vv.y;
                acc[i * 4 + 2] += pc * vv.z;
                acc[i * 4 + 3] += pc * vv.w;
            }
        }
        __syncthreads();
    }

    const float inv = 1.f / l;
    float* optr = O + (((size_t)(b * S_ + row)) * NH_ + h) * HD_ + half * 64;
#pragma unroll
    for (int i = 0; i < 16; i++) {
        float4 o = make_float4(acc[i * 4 + 0] * inv, acc[i * 4 + 1] * inv,
                               acc[i * 4 + 2] * inv, acc[i * 4 + 3] * inv);
        ((float4*)optr)[i] = o;
    }
}

// ---------------------------------------------------------------------------
// Launch
// ---------------------------------------------------------------------------
extern "C" void kernel_launch(void* const* d_in, const int* in_sizes, int n_in,
                              void* d_out, int out_size) {
    const float* hs   = (const float*)d_in[0];
    const float* cosp = (const float*)d_in[1];
    const float* sinp = (const float*)d_in[2];
    const float* Wq   = (const float*)d_in[4];
    const float* Wk   = (const float*)d_in[5];
    const float* Wv   = (const float*)d_in[6];
    const float* Wo   = (const float*)d_in[7];
    float* out = (float*)d_out;

    float *qbuf, *kbuf, *vbuf, *obuf;
    cudaGetSymbolAddress((void**)&qbuf, g_q);
    cudaGetSymbolAddress((void**)&kbuf, g_k);
    cudaGetSymbolAddress((void**)&vbuf, g_v);
    cudaGetSymbolAddress((void**)&obuf, g_o);

    __nv_bfloat16 *hs_h, *hs_l, *wq_h, *wq_l, *wk_h, *wk_l, *wv_h, *wv_l,
                  *wo_h, *wo_l, *ob_h, *ob_l;
    cudaGetSymbolAddress((void**)&hs_h, g_hs_h); cudaGetSymbolAddress((void**)&hs_l, g_hs_l);
    cudaGetSymbolAddress((void**)&wq_h, g_wq_h); cudaGetSymbolAddress((void**)&wq_l, g_wq_l);
    cudaGetSymbolAddress((void**)&wk_h, g_wk_h); cudaGetSymbolAddress((void**)&wk_l, g_wk_l);
    cudaGetSymbolAddress((void**)&wv_h, g_wv_h); cudaGetSymbolAddress((void**)&wv_l, g_wv_l);
    cudaGetSymbolAddress((void**)&wo_h, g_wo_h); cudaGetSymbolAddress((void**)&wo_l, g_wo_l);
    cudaGetSymbolAddress((void**)&ob_h, g_ob_h); cudaGetSymbolAddress((void**)&ob_l, g_ob_l);

    const int M = B_ * S_;   // 4096

    // Split conversions (inputs)
    split_kernel<<<(HS_ELEMS / 4 + 255) / 256, 256>>>(hs, hs_h, hs_l, HS_ELEMS);
    split_kernel<<<(WQ_ELEMS / 4 + 255) / 256, 256>>>(Wq, wq_h, wq_l, WQ_ELEMS);
    split_kernel<<<(WK_ELEMS / 4 + 255) / 256, 256>>>(Wk, wk_h, wk_l, WK_ELEMS);
    split_kernel<<<(WK_ELEMS / 4 + 255) / 256, 256>>>(Wv, wv_h, wv_l, WK_ELEMS);
    split_kernel<<<(WO_ELEMS / 4 + 255) / 256, 256>>>(Wo, wo_h, wo_l, WO_ELEMS);

    // QKV projections (tensor cores)
    gemm_mma<<<dim3((NH_ * HD_) / BN, M / BM), 256>>>(hs_h, hs_l, wq_h, wq_l, qbuf, M, NH_ * HD_, HID_);
    gemm_mma<<<dim3((NKV_ * HD_) / BN, M / BM), 256>>>(hs_h, hs_l, wk_h, wk_l, kbuf, M, NKV_ * HD_, HID_);
    gemm_mma<<<dim3((NKV_ * HD_) / BN, M / BM), 256>>>(hs_h, hs_l, wv_h, wv_l, vbuf, M, NKV_ * HD_, HID_);

    // RoPE on Q and K
    {
        int totq = B_ * S_ * NH_ * 64;
        rope_kernel<<<(totq + 255) / 256, 256>>>(qbuf, cosp, sinp, NH_, totq);
        int totk = B_ * S_ * NKV_ * 64;
        rope_kernel<<<(totk + 255) / 256, 256>>>(kbuf, cosp, sinp, NKV_, totk);
    }

    // Causal GQA flash attention (fp32)
    flash_kernel<<<dim3(S_ / FBM, NH_, B_), 128>>>(qbuf, kbuf, vbuf, obuf);

    // O projection (tensor cores)
    split_kernel<<<(HS_ELEMS / 4 + 255) / 256, 256>>>(obuf, ob_h, ob_l, HS_ELEMS);
    gemm_mma<<<dim3(HID_ / BN, M / BM), 256>>>(ob_h, ob_l, wo_h, wo_l, out, M, HID_, NH_ * HD_);
}

// round 3
// speedup vs baseline: 1.5543x; 1.0742x over previous
#include <cuda_runtime.h>
#include <cuda_bf16.h>
#include <cstdint>

// Problem constants
#define B_   2
#define S_   2048
#define HID_ 4096
#define NH_  32
#define NKV_ 8
#define HD_  128
#define NREP_ 4
#define SCALING_ 0.08838834764831843f   // 128^-0.5

// fp32 scratch
__device__ float g_q[(size_t)B_ * S_ * NH_  * HD_];
__device__ float g_k[(size_t)B_ * S_ * NKV_ * HD_];
__device__ float g_v[(size_t)B_ * S_ * NKV_ * HD_];
__device__ float g_o[(size_t)B_ * S_ * NH_  * HD_];

// bf16 split planes (hi / lo) for tensor-core GEMMs
#define HS_ELEMS  ((size_t)B_ * S_ * HID_)
#define WQ_ELEMS  ((size_t)NH_ * HD_ * HID_)
#define WK_ELEMS  ((size_t)NKV_ * HD_ * HID_)
#define WO_ELEMS  ((size_t)HID_ * NH_ * HD_)
__device__ __nv_bfloat16 g_hs_h[HS_ELEMS], g_hs_l[HS_ELEMS];
__device__ __nv_bfloat16 g_wq_h[WQ_ELEMS], g_wq_l[WQ_ELEMS];
__device__ __nv_bfloat16 g_wk_h[WK_ELEMS], g_wk_l[WK_ELEMS];
__device__ __nv_bfloat16 g_wv_h[WK_ELEMS], g_wv_l[WK_ELEMS];
__device__ __nv_bfloat16 g_wo_h[WO_ELEMS], g_wo_l[WO_ELEMS];
__device__ __nv_bfloat16 g_ob_h[HS_ELEMS], g_ob_l[HS_ELEMS];

// ---------------------------------------------------------------------------
// fp32 -> (bf16 hi, bf16 lo) split
// ---------------------------------------------------------------------------
__global__ void split_kernel(const float* __restrict__ x,
                             __nv_bfloat16* __restrict__ hi,
                             __nv_bfloat16* __restrict__ lo, size_t n) {
    size_t i = ((size_t)blockIdx.x * blockDim.x + threadIdx.x) * 4;
    if (i >= n) return;
    float4 v = *(const float4*)(x + i);
    float f[4] = {v.x, v.y, v.z, v.w};
#pragma unroll
    for (int j = 0; j < 4; j++) {
        __nv_bfloat16 h = __float2bfloat16(f[j]);
        hi[i + j] = h;
        lo[i + j] = __float2bfloat16(f[j] - __bfloat162float(h));
    }
}

// ---------------------------------------------------------------------------
// Pipelined split-bf16 NT GEMM: C[M,N] = (Ah+Al)[M,K] * (Bh+Bl)[N,K]^T
// 128x128 block, BK=16, 2-stage cp.async double buffer, ldmatrix frags.
// 256 threads = 8 warps (2x4), warp tile 64x32, 3 MMA planes (hh, hl, lh).
// ---------------------------------------------------------------------------
#define BM 128
#define BN 128
#define BKb 16
#define PAD 24   // row stride (bf16 elems) = 48B: conflict-free LDSM phases

__device__ __forceinline__ void mma16816(float c[4], uint32_t a0, uint32_t a1,
                                         uint32_t a2, uint32_t a3,
                                         uint32_t b0, uint32_t b1) {
    asm volatile(
        "mma.sync.aligned.m16n8k16.row.col.f32.bf16.bf16.f32 "
        "{%0,%1,%2,%3}, {%4,%5,%6,%7}, {%8,%9}, {%0,%1,%2,%3};\n"
        : "+f"(c[0]), "+f"(c[1]), "+f"(c[2]), "+f"(c[3])
        : "r"(a0), "r"(a1), "r"(a2), "r"(a3), "r"(b0), "r"(b1));
}

__device__ __forceinline__ void ldsm4(uint32_t& r0, uint32_t& r1, uint32_t& r2,
                                      uint32_t& r3, const void* p) {
    uint32_t a = (uint32_t)__cvta_generic_to_shared(p);
    asm volatile("ldmatrix.sync.aligned.m8n8.x4.shared.b16 {%0,%1,%2,%3}, [%4];\n"
                 : "=r"(r0), "=r"(r1), "=r"(r2), "=r"(r3) : "r"(a));
}

__device__ __forceinline__ void cp16(void* dst, const void* src) {
    uint32_t d = (uint32_t)__cvta_generic_to_shared(dst);
    asm volatile("cp.async.cg.shared.global [%0], [%1], 16;\n" :: "r"(d), "l"(src));
}

__global__ __launch_bounds__(256)
void gemm_mma(const __nv_bfloat16* __restrict__ Ah, const __nv_bfloat16* __restrict__ Al,
              const __nv_bfloat16* __restrict__ Bh, const __nv_bfloat16* __restrict__ Bl,
              float* __restrict__ C, int M, int N, int K) {
    __shared__ __nv_bfloat16 As[2][2][BM][PAD];   // [stage][plane][m][k]  24KB
    __shared__ __nv_bfloat16 Bs[2][2][BN][PAD];   // [stage][plane][n][k]  24KB

    const int tid = threadIdx.x;
    const int warp = tid >> 5, lane = tid & 31;
    const int g = lane >> 2, tg = lane & 3;
    const int warpM = warp >> 2, warpN = warp & 3;     // 2 x 4 warps
    const int bm = blockIdx.y * BM, bn = blockIdx.x * BN;

    // ldmatrix per-lane source rows
    const int a_r = lane & 15;             // row within 16-row tile
    const int a_k = (lane >> 4) * 8;       // k half
    const int b_r = lane & 7;              // n within 8
    const int b_n8 = ((lane >> 4) & 1) * 8;
    const int b_k8 = ((lane >> 3) & 1) * 8;

    // staging: 4 cp.async per thread per stage
    const int ld_row = tid >> 1;           // 0..127
    const int ld_chk = (tid & 1) * 8;      // bf16 elems (16B chunks)

    float c[4][4][4];
#pragma unroll
    for (int mi = 0; mi < 4; mi++)
#pragma unroll
        for (int ni = 0; ni < 4; ni++)
#pragma unroll
            for (int j = 0; j < 4; j++) c[mi][ni][j] = 0.f;

    const int niter = K / BKb;

    // prologue: stage 0
    {
        size_t ao = (size_t)(bm + ld_row) * K + ld_chk;
        size_t bo = (size_t)(bn + ld_row) * K + ld_chk;
        cp16(&As[0][0][ld_row][ld_chk], Ah + ao);
        cp16(&As[0][1][ld_row][ld_chk], Al + ao);
        cp16(&Bs[0][0][ld_row][ld_chk], Bh + bo);
        cp16(&Bs[0][1][ld_row][ld_chk], Bl + bo);
        asm volatile("cp.async.commit_group;\n");
    }

    for (int i = 0; i < niter; i++) {
        if (i + 1 < niter) {
            const int ns = (i + 1) & 1;
            const int k0 = (i + 1) * BKb;
            size_t ao = (size_t)(bm + ld_row) * K + k0 + ld_chk;
            size_t bo = (size_t)(bn + ld_row) * K + k0 + ld_chk;
            cp16(&As[ns][0][ld_row][ld_chk], Ah + ao);
            cp16(&As[ns][1][ld_row][ld_chk], Al + ao);
            cp16(&Bs[ns][0][ld_row][ld_chk], Bh + bo);
            cp16(&Bs[ns][1][ld_row][ld_chk], Bl + bo);
            asm volatile("cp.async.commit_group;\n");
            asm volatile("cp.async.wait_group 1;\n");
        } else {
            asm volatile("cp.async.wait_group 0;\n");
        }
        __syncthreads();

        const int s = i & 1;
        uint32_t aH[4][4], aL[4][4], bH[4][2], bL[4][2];
#pragma unroll
        for (int mi = 0; mi < 4; mi++) {
            int rb = warpM * 64 + mi * 16;
            ldsm4(aH[mi][0], aH[mi][1], aH[mi][2], aH[mi][3],
                  &As[s][0][rb + a_r][a_k]);
            ldsm4(aL[mi][0], aL[mi][1], aL[mi][2], aL[mi][3],
                  &As[s][1][rb + a_r][a_k]);
        }
#pragma unroll
        for (int np = 0; np < 2; np++) {
            int nb = warpN * 32 + np * 16;
            uint32_t r0, r1, r2, r3;
            ldsm4(r0, r1, r2, r3, &Bs[s][0][nb + b_r + b_n8][b_k8]);
            bH[np * 2][0] = r0; bH[np * 2][1] = r1;
            bH[np * 2 + 1][0] = r2; bH[np * 2 + 1][1] = r3;
            ldsm4(r0, r1, r2, r3, &Bs[s][1][nb + b_r + b_n8][b_k8]);
            bL[np * 2][0] = r0; bL[np * 2][1] = r1;
            bL[np * 2 + 1][0] = r2; bL[np * 2 + 1][1] = r3;
        }
#pragma unroll
        for (int mi = 0; mi < 4; mi++)
#pragma unroll
            for (int ni = 0; ni < 4; ni++) {
                mma16816(c[mi][ni], aH[mi][0], aH[mi][1], aH[mi][2], aH[mi][3],
                         bH[ni][0], bH[ni][1]);
                mma16816(c[mi][ni], aH[mi][0], aH[mi][1], aH[mi][2], aH[mi][3],
                         bL[ni][0], bL[ni][1]);
                mma16816(c[mi][ni], aL[mi][0], aL[mi][1], aL[mi][2], aL[mi][3],
                         bH[ni][0], bH[ni][1]);
            }
        __syncthreads();
    }

    // Epilogue
#pragma unroll
    for (int mi = 0; mi < 4; mi++) {
        int r0 = bm + warpM * 64 + mi * 16 + g;
#pragma unroll
        for (int ni = 0; ni < 4; ni++) {
            int cc = bn + warpN * 32 + ni * 8 + 2 * tg;
            *(float2*)(C + (size_t)r0 * N + cc) = make_float2(c[mi][ni][0], c[mi][ni][1]);
            *(float2*)(C + (size_t)(r0 + 8) * N + cc) = make_float2(c[mi][ni][2], c[mi][ni][3]);
        }
    }
}

// ---------------------------------------------------------------------------
// RoPE in-place
// ---------------------------------------------------------------------------
__global__ void rope_kernel(float* __restrict__ x,
                            const float* __restrict__ cosp,
                            const float* __restrict__ sinp,
                            int nheads, int total) {
    int idx = blockIdx.x * blockDim.x + threadIdx.x;
    if (idx >= total) return;
    int d  = idx & 63;
    int h  = (idx >> 6) % nheads;
    int bs = idx / (64 * nheads);
    float* row = x + (size_t)bs * nheads * HD_ + (size_t)h * HD_;
    const float* c = cosp + (size_t)bs * HD_;
    const float* s = sinp + (size_t)bs * HD_;
    float x1 = row[d], x2 = row[d + 64];
    row[d]      = x1 * c[d]      - x2 * s[d];
    row[d + 64] = x2 * c[d + 64] + x1 * s[d + 64];
}

// ---------------------------------------------------------------------------
// Flash attention (causal, GQA), fp32, online softmax (unchanged)
// ---------------------------------------------------------------------------
#define FBM 64
#define FBN 32

__global__ __launch_bounds__(128, 2)
void flash_kernel(const float* __restrict__ Q, const float* __restrict__ K,
                  const float* __restrict__ V, float* __restrict__ O) {
    __shared__ float Ksh[FBN][HD_];
    __shared__ float Vsh[FBN][HD_];

    const int b = blockIdx.z, h = blockIdx.y;
    const int qs = blockIdx.x * FBM;
    const int hk = h / NREP_;
    const int tid = threadIdx.x;
    const int lane = tid & 31, warp = tid >> 5;
    const int row  = qs + warp * 16 + (lane >> 1);
    const int half = lane & 1;

    const float* qptr = Q + (((size_t)(b * S_ + row)) * NH_ + h) * HD_ + half * 64;
    float4 qreg[16];
#pragma unroll
    for (int i = 0; i < 16; i++) {
        float4 v = ((const float4*)qptr)[i];
        v.x *= SCALING_; v.y *= SCALING_; v.z *= SCALING_; v.w *= SCALING_;
        qreg[i] = v;
    }

    float acc[64];
#pragma unroll
    for (int i = 0; i < 64; i++) acc[i] = 0.f;
    float m = -1e30f, l = 0.f;

    const int ntiles = (qs + FBM) / FBN;
    for (int j = 0; j < ntiles; j++) {
        const int ks = j * FBN;
        {
            int r  = tid >> 2;
            int cq = tid & 3;
            const float* kg = K + (((size_t)(b * S_ + ks + r)) * NKV_ + hk) * HD_;
            const float* vg = V + (((size_t)(b * S_ + ks + r)) * NKV_ + hk) * HD_;
#pragma unroll
            for (int i = 0; i < 8; i++) {
                int c4 = cq + i * 4;
                ((float4*)Ksh[r])[c4] = ((const float4*)kg)[c4];
                ((float4*)Vsh[r])[c4] = ((const float4*)vg)[c4];
            }
        }
        __syncthreads();

        float p[FBN];
        float mt = m;
#pragma unroll
        for (int c = 0; c < FBN; c++) {
            const float4* kr = (const float4*)(&Ksh[c][half * 64]);
            float s = 0.f;
#pragma unroll
            for (int i = 0; i < 16; i++) {
                float4 kv = kr[i];
                s += qreg[i].x * kv.x + qreg[i].y * kv.y
                   + qreg[i].z * kv.z + qreg[i].w * kv.w;
            }
            s += __shfl_xor_sync(0xffffffffu, s, 1);
            if (ks + c > row) s = -1e30f;
            p[c] = s;
            mt = fmaxf(mt, s);
        }

        const float scale = __expf(m - mt);
        m = mt;
        l *= scale;
#pragma unroll
        for (int i = 0; i < 64; i++) acc[i] *= scale;

#pragma unroll
        for (int c = 0; c < FBN; c++) {
            float pc = __expf(p[c] - mt);
            l += pc;
            const float4* vr = (const float4*)(&Vsh[c][half * 64]);
#pragma unroll
            for (int i = 0; i < 16; i++) {
                float4 vv = vr[i];
                acc[i * 4 + 0] += pc * vv.x;
                acc[i * 4 + 1] += pc * vv.y;
                acc[i * 4 + 2] += pc * vv.z;
                acc[i * 4 + 3] += pc * vv.w;
            }
        }
        __syncthreads();
    }

    const float inv = 1.f / l;
    float* optr = O + (((size_t)(b * S_ + row)) * NH_ + h) * HD_ + half * 64;
#pragma unroll
    for (int i = 0; i < 16; i++) {
        float4 o = make_float4(acc[i * 4 + 0] * inv, acc[i * 4 + 1] * inv,
                               acc[i * 4 + 2] * inv, acc[i * 4 + 3] * inv);
        ((float4*)optr)[i] = o;
    }
}

// ---------------------------------------------------------------------------
// Launch
// ---------------------------------------------------------------------------
extern "C" void kernel_launch(void* const* d_in, const int* in_sizes, int n_in,
                              void* d_out, int out_size) {
    const float* hs   = (const float*)d_in[0];
    const float* cosp = (const float*)d_in[1];
    const float* sinp = (const float*)d_in[2];
    const float* Wq   = (const float*)d_in[4];
    const float* Wk   = (const float*)d_in[5];
    const float* Wv   = (const float*)d_in[6];
    const float* Wo   = (const float*)d_in[7];
    float* out = (float*)d_out;

    float *qbuf, *kbuf, *vbuf, *obuf;
    cudaGetSymbolAddress((void**)&qbuf, g_q);
    cudaGetSymbolAddress((void**)&kbuf, g_k);
    cudaGetSymbolAddress((void**)&vbuf, g_v);
    cudaGetSymbolAddress((void**)&obuf, g_o);

    __nv_bfloat16 *hs_h, *hs_l, *wq_h, *wq_l, *wk_h, *wk_l, *wv_h, *wv_l,
                  *wo_h, *wo_l, *ob_h, *ob_l;
    cudaGetSymbolAddress((void**)&hs_h, g_hs_h); cudaGetSymbolAddress((void**)&hs_l, g_hs_l);
    cudaGetSymbolAddress((void**)&wq_h, g_wq_h); cudaGetSymbolAddress((void**)&wq_l, g_wq_l);
    cudaGetSymbolAddress((void**)&wk_h, g_wk_h); cudaGetSymbolAddress((void**)&wk_l, g_wk_l);
    cudaGetSymbolAddress((void**)&wv_h, g_wv_h); cudaGetSymbolAddress((void**)&wv_l, g_wv_l);
    cudaGetSymbolAddress((void**)&wo_h, g_wo_h); cudaGetSymbolAddress((void**)&wo_l, g_wo_l);
    cudaGetSymbolAddress((void**)&ob_h, g_ob_h); cudaGetSymbolAddress((void**)&ob_l, g_ob_l);

    const int M = B_ * S_;   // 4096

    // Split conversions
    split_kernel<<<(HS_ELEMS / 4 + 255) / 256, 256>>>(hs, hs_h, hs_l, HS_ELEMS);
    split_kernel<<<(WQ_ELEMS / 4 + 255) / 256, 256>>>(Wq, wq_h, wq_l, WQ_ELEMS);
    split_kernel<<<(WK_ELEMS / 4 + 255) / 256, 256>>>(Wk, wk_h, wk_l, WK_ELEMS);
    split_kernel<<<(WK_ELEMS / 4 + 255) / 256, 256>>>(Wv, wv_h, wv_l, WK_ELEMS);
    split_kernel<<<(WO_ELEMS / 4 + 255) / 256, 256>>>(Wo, wo_h, wo_l, WO_ELEMS);

    // QKV projections
    gemm_mma<<<dim3((NH_ * HD_) / BN, M / BM), 256>>>(hs_h, hs_l, wq_h, wq_l, qbuf, M, NH_ * HD_, HID_);
    gemm_mma<<<dim3((NKV_ * HD_) / BN, M / BM), 256>>>(hs_h, hs_l, wk_h, wk_l, kbuf, M, NKV_ * HD_, HID_);
    gemm_mma<<<dim3((NKV_ * HD_) / BN, M / BM), 256>>>(hs_h, hs_l, wv_h, wv_l, vbuf, M, NKV_ * HD_, HID_);

    // RoPE
    {
        int totq = B_ * S_ * NH_ * 64;
        rope_kernel<<<(totq + 255) / 256, 256>>>(qbuf, cosp, sinp, NH_, totq);
        int totk = B_ * S_ * NKV_ * 64;
        rope_kernel<<<(totk + 255) / 256, 256>>>(kbuf, cosp, sinp, NKV_, totk);
    }

    // Causal GQA flash attention (fp32)
    flash_kernel<<<dim3(S_ / FBM, NH_, B_), 128>>>(qbuf, kbuf, vbuf, obuf);

    // O projection
    split_kernel<<<(HS_ELEMS / 4 + 255) / 256, 256>>>(obuf, ob_h, ob_l, HS_ELEMS);
    gemm_mma<<<dim3(HID_ / BN, M / BM), 256>>>(ob_h, ob_l, wo_h, wo_l, out, M, HID_, NH_ * HD_);
}

// round 5
// speedup vs baseline: 3.3923x; 2.1825x over previous
#include <cuda_runtime.h>
#include <cuda_bf16.h>
#include <cstdint>

// Problem constants
#define B_   2
#define S_   2048
#define HID_ 4096
#define NH_  32
#define NKV_ 8
#define HD_  128
#define NREP_ 4
#define SCALING_ 0.08838834764831843f   // 128^-0.5

// fp32 scratch
__device__ float g_q[(size_t)B_ * S_ * NH_  * HD_];
__device__ float g_k[(size_t)B_ * S_ * NKV_ * HD_];
__device__ float g_v[(size_t)B_ * S_ * NKV_ * HD_];
__device__ float g_o[(size_t)B_ * S_ * NH_  * HD_];

// bf16 split planes
#define HS_ELEMS  ((size_t)B_ * S_ * HID_)
#define WQ_ELEMS  ((size_t)NH_ * HD_ * HID_)
#define WK_ELEMS  ((size_t)NKV_ * HD_ * HID_)
#define WO_ELEMS  ((size_t)HID_ * NH_ * HD_)
#define KV_ELEMS  ((size_t)B_ * S_ * NKV_ * HD_)
__device__ __nv_bfloat16 g_hs_h[HS_ELEMS], g_hs_l[HS_ELEMS];
__device__ __nv_bfloat16 g_wq_h[WQ_ELEMS], g_wq_l[WQ_ELEMS];
__device__ __nv_bfloat16 g_wk_h[WK_ELEMS], g_wk_l[WK_ELEMS];
__device__ __nv_bfloat16 g_wv_h[WK_ELEMS], g_wv_l[WK_ELEMS];
__device__ __nv_bfloat16 g_wo_h[WO_ELEMS], g_wo_l[WO_ELEMS];
__device__ __nv_bfloat16 g_ob_h[HS_ELEMS], g_ob_l[HS_ELEMS];
// attention bf16 planes (post-rope)
__device__ __nv_bfloat16 g_qh[HS_ELEMS], g_ql[HS_ELEMS];
__device__ __nv_bfloat16 g_kh[KV_ELEMS], g_kl[KV_ELEMS];
__device__ __nv_bfloat16 g_vth[KV_ELEMS], g_vtl[KV_ELEMS];  // [b][hk][d][s]

// ---------------------------------------------------------------------------
// helpers
// ---------------------------------------------------------------------------
static __device__ __forceinline__ uint32_t smem_u32(const void* p) {
    uint32_t a;
    asm("{ .reg .u64 t; cvta.to.shared.u64 t, %1; cvt.u32.u64 %0, t; }"
        : "=r"(a) : "l"(p));
    return a;
}
static __device__ __forceinline__ void cp16(uint32_t dst, const void* src) {
    asm volatile("cp.async.cg.shared.global [%0], [%1], 16;\n" :: "r"(dst), "l"(src));
}
__device__ __forceinline__ void mma16816(float c[4], uint32_t a0, uint32_t a1,
                                         uint32_t a2, uint32_t a3,
                                         uint32_t b0, uint32_t b1) {
    asm volatile(
        "mma.sync.aligned.m16n8k16.row.col.f32.bf16.bf16.f32 "
        "{%0,%1,%2,%3}, {%4,%5,%6,%7}, {%8,%9}, {%0,%1,%2,%3};\n"
        : "+f"(c[0]), "+f"(c[1]), "+f"(c[2]), "+f"(c[3])
        : "r"(a0), "r"(a1), "r"(a2), "r"(a3), "r"(b0), "r"(b1));
}
__device__ __forceinline__ void ldsm4(uint32_t& r0, uint32_t& r1, uint32_t& r2,
                                      uint32_t& r3, const void* p) {
    uint32_t a = (uint32_t)__cvta_generic_to_shared(p);
    asm volatile("ldmatrix.sync.aligned.m8n8.x4.shared.b16 {%0,%1,%2,%3}, [%4];\n"
                 : "=r"(r0), "=r"(r1), "=r"(r2), "=r"(r3) : "r"(a));
}
// pack two fp32 into bf16x2 (lo, hi), round-to-nearest
static __device__ __forceinline__ uint32_t pk_bf2(float lo, float hi) {
    __nv_bfloat162 t = __floats2bfloat162_rn(lo, hi);
    return *reinterpret_cast<uint32_t*>(&t);
}

// ---------------------------------------------------------------------------
// fp32 -> (bf16 hi, bf16 lo) split
// ---------------------------------------------------------------------------
__global__ void split_kernel(const float* __restrict__ x,
                             __nv_bfloat16* __restrict__ hi,
                             __nv_bfloat16* __restrict__ lo, size_t n) {
    size_t i = ((size_t)blockIdx.x * blockDim.x + threadIdx.x) * 4;
    if (i >= n) return;
    float4 v = *(const float4*)(x + i);
    float f[4] = {v.x, v.y, v.z, v.w};
#pragma unroll
    for (int j = 0; j < 4; j++) {
        __nv_bfloat16 h = __float2bfloat16(f[j]);
        hi[i + j] = h;
        lo[i + j] = __float2bfloat16(f[j] - __bfloat162float(h));
    }
}

// split + transpose V: in [b*S][NKV*HD] fp32 -> out [b][hk][d][s] bf16 h/l
__global__ void splitT_v(const float* __restrict__ v,
                         __nv_bfloat16* __restrict__ vh,
                         __nv_bfloat16* __restrict__ vl) {
    size_t idx = (size_t)blockIdx.x * blockDim.x + threadIdx.x;
    if (idx >= KV_ELEMS) return;
    int s  = idx & (S_ - 1);
    size_t r = idx >> 11;
    int d  = r & (HD_ - 1);  r >>= 7;
    int hk = r & (NKV_ - 1);
    int b  = (int)(r >> 3);
    float x = v[((size_t)(b * S_ + s) * NKV_ + hk) * HD_ + d];
    __nv_bfloat16 h = __float2bfloat16(x);
    vh[idx] = h;
    vl[idx] = __float2bfloat16(x - __bfloat162float(h));
}

// ---------------------------------------------------------------------------
// Split-bf16 NT GEMM, mma.sync, BK=32 per stage, 2-stage cp.async.
// 256 threads (8 warps 2x4), warp tile 64x32, 3 planes.
// ---------------------------------------------------------------------------
#define BM 128
#define BN 128
#define GK 32
#define GPAD 40
#define GA_ELEMS 20480   // 2 stages * 2 planes * 128 * 40
#define GSMEM_B ((GA_ELEMS * 2) * 2)   // bytes: 81920

__global__ __launch_bounds__(256)
void gemm_mma(const __nv_bfloat16* __restrict__ Ah, const __nv_bfloat16* __restrict__ Al,
              const __nv_bfloat16* __restrict__ Bh, const __nv_bfloat16* __restrict__ Bl,
              float* __restrict__ C, int M, int N, int K) {
    extern __shared__ __nv_bfloat16 gsm[];
    const uint32_t sb = smem_u32(gsm);

    const int tid = threadIdx.x;
    const int warp = tid >> 5, lane = tid & 31;
    const int g = lane >> 2, tg = lane & 3;
    const int warpM = warp >> 2, warpN = warp & 3;
    const int bm = blockIdx.y * BM, bn = blockIdx.x * BN;

    const int a_r = lane & 15;
    const int a_k = (lane >> 4) * 8;
    const int b_r = lane & 7;
    const int b_n8 = ((lane >> 4) & 1) * 8;
    const int b_k8 = ((lane >> 3) & 1) * 8;

    float c[4][4][4];
#pragma unroll
    for (int mi = 0; mi < 4; mi++)
#pragma unroll
        for (int ni = 0; ni < 4; ni++)
#pragma unroll
            for (int j = 0; j < 4; j++) c[mi][ni][j] = 0.f;

    const int niter = K / GK;

    auto load_stage = [&](int s, int k0) {
#pragma unroll
        for (int i = 0; i < 2; i++) {
            int j = tid + (i << 8);
            int row = j >> 2, col = (j & 3) * 8;
            size_t ao = (size_t)(bm + row) * K + k0 + col;
            size_t bo = (size_t)(bn + row) * K + k0 + col;
            uint32_t da = sb + (uint32_t)((((s * 2) * 128 + row) * GPAD + col) * 2);
            uint32_t db = sb + (uint32_t)((GA_ELEMS + ((s * 2) * 128 + row) * GPAD + col) * 2);
            cp16(da, Ah + ao);
            cp16(da + 128 * GPAD * 2, Al + ao);
            cp16(db, Bh + bo);
            cp16(db + 128 * GPAD * 2, Bl + bo);
        }
        asm volatile("cp.async.commit_group;\n");
    };

    load_stage(0, 0);

    for (int i = 0; i < niter; i++) {
        if (i + 1 < niter) {
            load_stage((i + 1) & 1, (i + 1) * GK);
            asm volatile("cp.async.wait_group 1;\n");
        } else {
            asm volatile("cp.async.wait_group 0;\n");
        }
        __syncthreads();

        const int s = i & 1;
        const __nv_bfloat16* Asm = gsm + (size_t)(s * 2) * 128 * GPAD;
        const __nv_bfloat16* Bsm = gsm + GA_ELEMS + (size_t)(s * 2) * 128 * GPAD;
#pragma unroll
        for (int kk = 0; kk < 2; kk++) {
            const int kb = kk * 16;
            uint32_t aH[4][4], aL[4][4], bH[4][2], bL[4][2];
#pragma unroll
            for (int mi = 0; mi < 4; mi++) {
                int rb = warpM * 64 + mi * 16;
                ldsm4(aH[mi][0], aH[mi][1], aH[mi][2], aH[mi][3],
                      Asm + (size_t)(rb + a_r) * GPAD + kb + a_k);
                ldsm4(aL[mi][0], aL[mi][1], aL[mi][2], aL[mi][3],
                      Asm + 128 * GPAD + (size_t)(rb + a_r) * GPAD + kb + a_k);
            }
#pragma unroll
            for (int np = 0; np < 2; np++) {
                int nb = warpN * 32 + np * 16;
                uint32_t r0, r1, r2, r3;
                ldsm4(r0, r1, r2, r3,
                      Bsm + (size_t)(nb + b_r + b_n8) * GPAD + kb + b_k8);
                bH[np * 2][0] = r0; bH[np * 2][1] = r1;
                bH[np * 2 + 1][0] = r2; bH[np * 2 + 1][1] = r3;
                ldsm4(r0, r1, r2, r3,
                      Bsm + 128 * GPAD + (size_t)(nb + b_r + b_n8) * GPAD + kb + b_k8);
                bL[np * 2][0] = r0; bL[np * 2][1] = r1;
                bL[np * 2 + 1][0] = r2; bL[np * 2 + 1][1] = r3;
            }
#pragma unroll
            for (int mi = 0; mi < 4; mi++)
#pragma unroll
                for (int ni = 0; ni < 4; ni++) {
                    mma16816(c[mi][ni], aH[mi][0], aH[mi][1], aH[mi][2], aH[mi][3],
                             bH[ni][0], bH[ni][1]);
                    mma16816(c[mi][ni], aH[mi][0], aH[mi][1], aH[mi][2], aH[mi][3],
                             bL[ni][0], bL[ni][1]);
                    mma16816(c[mi][ni], aL[mi][0], aL[mi][1], aL[mi][2], aL[mi][3],
                             bH[ni][0], bH[ni][1]);
                }
        }
        __syncthreads();
    }

#pragma unroll
    for (int mi = 0; mi < 4; mi++) {
        int r0 = bm + warpM * 64 + mi * 16 + g;
#pragma unroll
        for (int ni = 0; ni < 4; ni++) {
            int cc = bn + warpN * 32 + ni * 8 + 2 * tg;
            *(float2*)(C + (size_t)r0 * N + cc) = make_float2(c[mi][ni][0], c[mi][ni][1]);
            *(float2*)(C + (size_t)(r0 + 8) * N + cc) = make_float2(c[mi][ni][2], c[mi][ni][3]);
        }
    }
}

// ---------------------------------------------------------------------------
// RoPE in-place
// ---------------------------------------------------------------------------
__global__ void rope_kernel(float* __restrict__ x,
                            const float* __restrict__ cosp,
                            const float* __restrict__ sinp,
                            int nheads, int total) {
    int idx = blockIdx.x * blockDim.x + threadIdx.x;
    if (idx >= total) return;
    int d  = idx & 63;
    int h  = (idx >> 6) % nheads;
    int bs = idx / (64 * nheads);
    float* row = x + (size_t)bs * nheads * HD_ + (size_t)h * HD_;
    const float* c = cosp + (size_t)bs * HD_;
    const float* s = sinp + (size_t)bs * HD_;
    float x1 = row[d], x2 = row[d + 64];
    row[d]      = x1 * c[d]      - x2 * s[d];
    row[d + 64] = x2 * c[d + 64] + x1 * s[d + 64];
}

// ---------------------------------------------------------------------------
// Flash attention via split-bf16 mma.sync.
// CTA: 128 threads (4 warps), 64 q rows (16/warp), K-tile 64 keys.
// SMEM: Qh/Ql [64][136], Kh/Kl [64][136], Vth/Vtl [128][72] (d-major).
// ---------------------------------------------------------------------------
#define FQH 0
#define FQL 8704
#define FKH 17408
#define FKL 26112
#define FVH 34816
#define FVL 44032
#define FSMEM_B 106496

__global__ __launch_bounds__(128)
void flash_mma(const __nv_bfloat16* __restrict__ Qh, const __nv_bfloat16* __restrict__ Ql,
               const __nv_bfloat16* __restrict__ Kh, const __nv_bfloat16* __restrict__ Kl,
               const __nv_bfloat16* __restrict__ Vth, const __nv_bfloat16* __restrict__ Vtl,
               float* __restrict__ O) {
    extern __shared__ __nv_bfloat16 fsm[];
    const uint32_t sb = smem_u32(fsm);

    const int b = blockIdx.z, h = blockIdx.y, qt = blockIdx.x;
    const int qs = qt * 64, hk = h >> 2;
    const int tid = threadIdx.x;
    const int warp = tid >> 5, lane = tid & 31;
    const int g = lane >> 2, tg = lane & 3;

    const int a_r = lane & 15;
    const int a_k = (lane >> 4) * 8;
    const int b_r = lane & 7;
    const int b_n8 = ((lane >> 4) & 1) * 8;
    const int b_k8 = ((lane >> 3) & 1) * 8;

    // ---- load Q tile (once) ----
#pragma unroll
    for (int i = 0; i < 8; i++) {
        int j = tid + (i << 7);
        int row = j >> 4, kc = j & 15;
        uint32_t d = sb + (uint32_t)((row * 136 + kc * 8) * 2);
        size_t src = ((size_t)(b * S_ + qs + row) * NH_ + h) * HD_ + kc * 8;
        cp16(d + FQH * 2, Qh + src);
        cp16(d + FQL * 2, Ql + src);
    }
    asm volatile("cp.async.commit_group;\n");

    float o[16][4];
#pragma unroll
    for (int nt = 0; nt < 16; nt++)
#pragma unroll
        for (int j = 0; j < 4; j++) o[nt][j] = 0.f;
    float m0 = -1e30f, m1 = -1e30f, l0 = 0.f, l1 = 0.f;

    const int qr0 = qs + warp * 16 + g;
    const int qr1 = qr0 + 8;
    const int ntiles = qt + 1;

    for (int j = 0; j < ntiles; j++) {
        const int ks = j * 64;
        // ---- load K and Vt tiles ----
#pragma unroll
        for (int i = 0; i < 8; i++) {
            int jj = tid + (i << 7);
            int krow = jj >> 4, kkc = jj & 15;
            uint32_t dk = sb + (uint32_t)((krow * 136 + kkc * 8) * 2);
            size_t ksrc = ((size_t)(b * S_ + ks + krow) * NKV_ + hk) * HD_ + kkc * 8;
            cp16(dk + FKH * 2, Kh + ksrc);
            cp16(dk + FKL * 2, Kl + ksrc);
            int vd = jj >> 3, vc = jj & 7;
            uint32_t dv = sb + (uint32_t)((vd * 72 + vc * 8) * 2);
            size_t vsrc = ((size_t)(b * NKV_ + hk) * HD_ + vd) * S_ + ks + vc * 8;
            cp16(dv + FVH * 2, Vth + vsrc);
            cp16(dv + FVL * 2, Vtl + vsrc);
        }
        asm volatile("cp.async.commit_group;\n");
        asm volatile("cp.async.wait_group 0;\n");
        __syncthreads();

        // ---- S = Q K^T (3-plane) ----
        float S4[8][4];
#pragma unroll
        for (int nt = 0; nt < 8; nt++)
#pragma unroll
            for (int cc = 0; cc < 4; cc++) S4[nt][cc] = 0.f;

#pragma unroll
        for (int dk = 0; dk < 8; dk++) {
            uint32_t aH[4], aL[4];
            ldsm4(aH[0], aH[1], aH[2], aH[3],
                  fsm + FQH + (size_t)(warp * 16 + a_r) * 136 + dk * 16 + a_k);
            ldsm4(aL[0], aL[1], aL[2], aL[3],
                  fsm + FQL + (size_t)(warp * 16 + a_r) * 136 + dk * 16 + a_k);
#pragma unroll
            for (int np = 0; np < 4; np++) {
                int nb = np * 16;
                uint32_t h0, h1, h2, h3, l0r, l1r, l2r, l3r;
                ldsm4(h0, h1, h2, h3,
                      fsm + FKH + (size_t)(nb + b_r + b_n8) * 136 + dk * 16 + b_k8);
                ldsm4(l0r, l1r, l2r, l3r,
                      fsm + FKL + (size_t)(nb + b_r + b_n8) * 136 + dk * 16 + b_k8);
                mma16816(S4[2 * np],     aH[0], aH[1], aH[2], aH[3], h0, h1);
                mma16816(S4[2 * np],     aH[0], aH[1], aH[2], aH[3], l0r, l1r);
                mma16816(S4[2 * np],     aL[0], aL[1], aL[2], aL[3], h0, h1);
                mma16816(S4[2 * np + 1], aH[0], aH[1], aH[2], aH[3], h2, h3);
                mma16816(S4[2 * np + 1], aH[0], aH[1], aH[2], aH[3], l2r, l3r);
                mma16816(S4[2 * np + 1], aL[0], aL[1], aL[2], aL[3], h2, h3);
            }
        }

        // ---- scale + mask + online softmax ----
        float mx0 = -1e30f, mx1 = -1e30f;
        const bool diag = (j == ntiles - 1);
#pragma unroll
        for (int nt = 0; nt < 8; nt++) {
#pragma unroll
            for (int cc = 0; cc < 4; cc++) {
                float v = S4[nt][cc] * SCALING_;
                if (diag) {
                    int kcol = ks + nt * 8 + 2 * tg + (cc & 1);
                    int qr = (cc < 2) ? qr0 : qr1;
                    if (kcol > qr) v = -1e30f;
                }
                S4[nt][cc] = v;
                if (cc < 2) mx0 = fmaxf(mx0, v); else mx1 = fmaxf(mx1, v);
            }
        }
        mx0 = fmaxf(mx0, __shfl_xor_sync(0xffffffffu, mx0, 1));
        mx0 = fmaxf(mx0, __shfl_xor_sync(0xffffffffu, mx0, 2));
        mx1 = fmaxf(mx1, __shfl_xor_sync(0xffffffffu, mx1, 1));
        mx1 = fmaxf(mx1, __shfl_xor_sync(0xffffffffu, mx1, 2));
        const float mt0 = fmaxf(m0, mx0), mt1 = fmaxf(m1, mx1);
        const float sc0 = __expf(m0 - mt0), sc1 = __expf(m1 - mt1);
        m0 = mt0; m1 = mt1;

        float rs0 = 0.f, rs1 = 0.f;
#pragma unroll
        for (int nt = 0; nt < 8; nt++) {
            float p0 = __expf(S4[nt][0] - mt0);
            float p1 = __expf(S4[nt][1] - mt0);
            float p2 = __expf(S4[nt][2] - mt1);
            float p3 = __expf(S4[nt][3] - mt1);
            S4[nt][0] = p0; S4[nt][1] = p1; S4[nt][2] = p2; S4[nt][3] = p3;
            rs0 += p0 + p1; rs1 += p2 + p3;
        }
        rs0 += __shfl_xor_sync(0xffffffffu, rs0, 1);
        rs0 += __shfl_xor_sync(0xffffffffu, rs0, 2);
        rs1 += __shfl_xor_sync(0xffffffffu, rs1, 1);
        rs1 += __shfl_xor_sync(0xffffffffu, rs1, 2);
        l0 = l0 * sc0 + rs0;
        l1 = l1 * sc1 + rs1;
#pragma unroll
        for (int nt = 0; nt < 16; nt++) {
            o[nt][0] *= sc0; o[nt][1] *= sc0;
            o[nt][2] *= sc1; o[nt][3] *= sc1;
        }

        // ---- O += P V (3-plane, P split in registers) ----
#pragma unroll
        for (int kt = 0; kt < 4; kt++) {
            uint32_t aPh[4], aPl[4];
#pragma unroll
            for (int half = 0; half < 2; half++) {      // S tiles 2kt, 2kt+1
                const float* sv = S4[2 * kt + half];
                uint32_t p01 = pk_bf2(sv[0], sv[1]);
                uint32_t p23 = pk_bf2(sv[2], sv[3]);
                float r0f = sv[0] - __uint_as_float(p01 << 16);
                float r1f = sv[1] - __uint_as_float(p01 & 0xffff0000u);
                float r2f = sv[2] - __uint_as_float(p23 << 16);
                float r3f = sv[3] - __uint_as_float(p23 & 0xffff0000u);
                aPh[0 + 2 * half] = p01;
                aPh[1 + 2 * half] = p23;
                aPl[0 + 2 * half] = pk_bf2(r0f, r1f);
                aPl[1 + 2 * half] = pk_bf2(r2f, r3f);
            }
            // reorder: frag = {a0,a1,a2,a3} = {t0.c01, t0.c23, t1.c01, t1.c23}
            // built above as [0]=t0.c01 [1]=t0.c23 [2]=t1.c01 [3]=t1.c23  (ok)
#pragma unroll
            for (int np = 0; np < 8; np++) {
                int nb = np * 16;
                uint32_t h0, h1, h2, h3, l0r, l1r, l2r, l3r;
                ldsm4(h0, h1, h2, h3,
                      fsm + FVH + (size_t)(nb + b_r + b_n8) * 72 + kt * 16 + b_k8);
                ldsm4(l0r, l1r, l2r, l3r,
                      fsm + FVL + (size_t)(nb + b_r + b_n8) * 72 + kt * 16 + b_k8);
                mma16816(o[2 * np],     aPh[0], aPh[1], aPh[2], aPh[3], h0, h1);
                mma16816(o[2 * np],     aPh[0], aPh[1], aPh[2], aPh[3], l0r, l1r);
                mma16816(o[2 * np],     aPl[0], aPl[1], aPl[2], aPl[3], h0, h1);
                mma16816(o[2 * np + 1], aPh[0], aPh[1], aPh[2], aPh[3], h2, h3);
                mma16816(o[2 * np + 1], aPh[0], aPh[1], aPh[2], aPh[3], l2r, l3r);
                mma16816(o[2 * np + 1], aPl[0], aPl[1], aPl[2], aPl[3], h2, h3);
            }
        }
        __syncthreads();
    }

    // ---- writeback ----
    const float inv0 = 1.f / l0, inv1 = 1.f / l1;
    float* o0 = O + (size_t)(b * S_ + qr0) * (NH_ * HD_) + h * HD_;
    float* o1 = O + (size_t)(b * S_ + qr1) * (NH_ * HD_) + h * HD_;
#pragma unroll
    for (int nt = 0; nt < 16; nt++) {
        int cc = nt * 8 + 2 * tg;
        *(float2*)(o0 + cc) = make_float2(o[nt][0] * inv0, o[nt][1] * inv0);
        *(float2*)(o1 + cc) = make_float2(o[nt][2] * inv1, o[nt][3] * inv1);
    }
}

// ---------------------------------------------------------------------------
// Launch
// ---------------------------------------------------------------------------
extern "C" void kernel_launch(void* const* d_in, const int* in_sizes, int n_in,
                              void* d_out, int out_size) {
    const float* hs   = (const float*)d_in[0];
    const float* cosp = (const float*)d_in[1];
    const float* sinp = (const float*)d_in[2];
    const float* Wq   = (const float*)d_in[4];
    const float* Wk   = (const float*)d_in[5];
    const float* Wv   = (const float*)d_in[6];
    const float* Wo   = (const float*)d_in[7];
    float* out = (float*)d_out;

    float *qbuf, *kbuf, *vbuf, *obuf;
    cudaGetSymbolAddress((void**)&qbuf, g_q);
    cudaGetSymbolAddress((void**)&kbuf, g_k);
    cudaGetSymbolAddress((void**)&vbuf, g_v);
    cudaGetSymbolAddress((void**)&obuf, g_o);

    __nv_bfloat16 *hs_h, *hs_l, *wq_h, *wq_l, *wk_h, *wk_l, *wv_h, *wv_l,
                  *wo_h, *wo_l, *ob_h, *ob_l, *qh, *ql, *kh, *kl, *vth, *vtl;
    cudaGetSymbolAddress((void**)&hs_h, g_hs_h); cudaGetSymbolAddress((void**)&hs_l, g_hs_l);
    cudaGetSymbolAddress((void**)&wq_h, g_wq_h); cudaGetSymbolAddress((void**)&wq_l, g_wq_l);
    cudaGetSymbolAddress((void**)&wk_h, g_wk_h); cudaGetSymbolAddress((void**)&wk_l, g_wk_l);
    cudaGetSymbolAddress((void**)&wv_h, g_wv_h); cudaGetSymbolAddress((void**)&wv_l, g_wv_l);
    cudaGetSymbolAddress((void**)&wo_h, g_wo_h); cudaGetSymbolAddress((void**)&wo_l, g_wo_l);
    cudaGetSymbolAddress((void**)&ob_h, g_ob_h); cudaGetSymbolAddress((void**)&ob_l, g_ob_l);
    cudaGetSymbolAddress((void**)&qh, g_qh); cudaGetSymbolAddress((void**)&ql, g_ql);
    cudaGetSymbolAddress((void**)&kh, g_kh); cudaGetSymbolAddress((void**)&kl, g_kl);
    cudaGetSymbolAddress((void**)&vth, g_vth); cudaGetSymbolAddress((void**)&vtl, g_vtl);

    cudaFuncSetAttribute(gemm_mma, cudaFuncAttributeMaxDynamicSharedMemorySize, GSMEM_B);
    cudaFuncSetAttribute(flash_mma, cudaFuncAttributeMaxDynamicSharedMemorySize, FSMEM_B);

    const int M = B_ * S_;   // 4096

    // Split conversions (inputs)
    split_kernel<<<(HS_ELEMS / 4 + 255) / 256, 256>>>(hs, hs_h, hs_l, HS_ELEMS);
    split_kernel<<<(WQ_ELEMS / 4 + 255) / 256, 256>>>(Wq, wq_h, wq_l, WQ_ELEMS);
    split_kernel<<<(WK_ELEMS / 4 + 255) / 256, 256>>>(Wk, wk_h, wk_l, WK_ELEMS);
    split_kernel<<<(WK_ELEMS / 4 + 255) / 256, 256>>>(Wv, wv_h, wv_l, WK_ELEMS);
    split_kernel<<<(WO_ELEMS / 4 + 255) / 256, 256>>>(Wo, wo_h, wo_l, WO_ELEMS);

    // QKV projections
    gemm_mma<<<dim3((NH_ * HD_) / BN, M / BM), 256, GSMEM_B>>>(hs_h, hs_l, wq_h, wq_l, qbuf, M, NH_ * HD_, HID_);
    gemm_mma<<<dim3((NKV_ * HD_) / BN, M / BM), 256, GSMEM_B>>>(hs_h, hs_l, wk_h, wk_l, kbuf, M, NKV_ * HD_, HID_);
    gemm_mma<<<dim3((NKV_ * HD_) / BN, M / BM), 256, GSMEM_B>>>(hs_h, hs_l, wv_h, wv_l, vbuf, M, NKV_ * HD_, HID_);

    // RoPE
    {
        int totq = B_ * S_ * NH_ * 64;
        rope_kernel<<<(totq + 255) / 256, 256>>>(qbuf, cosp, sinp, NH_, totq);
        int totk = B_ * S_ * NKV_ * 64;
        rope_kernel<<<(totk + 255) / 256, 256>>>(kbuf, cosp, sinp, NKV_, totk);
    }

    // Split post-rope Q/K; split+transpose V
    split_kernel<<<(HS_ELEMS / 4 + 255) / 256, 256>>>(qbuf, qh, ql, HS_ELEMS);
    split_kernel<<<(KV_ELEMS / 4 + 255) / 256, 256>>>(kbuf, kh, kl, KV_ELEMS);
    splitT_v<<<(KV_ELEMS + 255) / 256, 256>>>(vbuf, vth, vtl);

    // Flash attention (split-bf16 mma)
    flash_mma<<<dim3(S_ / 64, NH_, B_), 128, FSMEM_B>>>(qh, ql, kh, kl, vth, vtl, obuf);

    // O projection
    split_kernel<<<(HS_ELEMS / 4 + 255) / 256, 256>>>(obuf, ob_h, ob_l, HS_ELEMS);
    gemm_mma<<<dim3(HID_ / BN, M / BM), 256, GSMEM_B>>>(ob_h, ob_l, wo_h, wo_l, out, M, HID_, NH_ * HD_);
}